// round 9
// baseline (speedup 1.0000x reference)
#include <cuda_runtime.h>
#include <cstdint>

// 7x7 single-out-channel conv via legacy mma.sync tf32 implicit GEMM.
// Round 9: 256 threads / 8 warps per CTA, ONE 16-pixel m-tile per warp
// (halves per-thread registers -> 2 CTAs/SM, 16 warps/SM).
// D_o[pix, dw] accumulates over dh in a 7-deep register ring; epilogue
// shift-sums over dw through padded smem. CTA = 32 output rows of one image.

#define HW 128
#define HW2 (HW * HW)
#define C_DIM 64
#define BAND 32
#define NT 256

static __device__ __forceinline__ uint32_t f2tf(float v) {
    uint32_t r;
    asm("cvt.rna.tf32.f32 %0, %1;" : "=r"(r) : "f"(v));
    return r;
}

static __device__ __forceinline__ void mma8(float (&d)[4], const uint32_t (&a)[4],
                                            uint32_t b0, uint32_t b1) {
    asm("mma.sync.aligned.m16n8k8.row.col.f32.tf32.tf32.f32 "
        "{%0,%1,%2,%3}, {%4,%5,%6,%7}, {%8,%9}, {%0,%1,%2,%3};"
        : "+f"(d[0]), "+f"(d[1]), "+f"(d[2]), "+f"(d[3])
        : "r"(a[0]), "r"(a[1]), "r"(a[2]), "r"(a[3]), "r"(b0), "r"(b1));
}

__global__ void __launch_bounds__(NT, 2)
conv7x7_mma256(const float* __restrict__ x, const float* __restrict__ w,
               const float* __restrict__ bias, float* __restrict__ out)
{
    __shared__ unsigned long long s_bw[7][8][32];  // B fragments per (dh, kstep, lane)
    __shared__ float s_epi[2][HW * 9];             // epilogue shift buffer (pitch 9)

    const int tid  = threadIdx.x;
    const int wid  = tid >> 5;        // 0..7: m-tile index
    const int lane = tid & 31;
    const int g    = lane >> 2;       // pixel-within-tile (rows g, g+8)
    const int q    = lane & 3;        // k-quad
    const int cq2  = 2 * q;           // channel pair base / dw pair base
    const int pb   = wid * 16 + g;    // pixel base of this thread's tile rows

    const int b      = blockIdx.y;
    const int ostart = blockIdx.x * BAND;
    const int oend   = ostart + BAND;
    const int rlo    = (ostart - 3 < 0) ? 0 : ostart - 3;
    const int rhi    = (oend + 2 > HW - 1) ? HW - 1 : oend + 2;

    // ---- stage B fragments: k-index kq -> channel ks*8 + perm(kq),
    //      perm(q)=2q, perm(q+4)=2q+1 (matches A-side LDG pairing) ----
    for (int i = tid; i < 7 * 8 * 32; i += NT) {
        const int dh  = i >> 8;
        const int rem = i & 255;
        const int ks  = rem >> 5;
        const int ln  = rem & 31;
        const int qq  = ln & 3;
        const int dw  = ln >> 2;              // n-index
        const int c0  = ks * 8 + 2 * qq;
        unsigned long long lo = 0, hi = 0;
        if (dw < 7) {
            lo = f2tf(w[c0 * 49 + dh * 7 + dw]);
            hi = f2tf(w[(c0 + 1) * 49 + dh * 7 + dw]);
        }
        s_bw[dh][ks][ln] = lo | (hi << 32);
    }
    __syncthreads();

    const float bv = bias[0];
    const float* xb = x + (size_t)b * C_DIM * HW2;
    float* outb = out + (size_t)b * HW2;

    float acc[7][4];
#pragma unroll
    for (int j = 0; j < 7; ++j)
#pragma unroll
        for (int k2 = 0; k2 < 4; ++k2) acc[j][k2] = 0.f;

    uint32_t ab0[8][4], ab1[8][4];
    int epar = 0;

#define LOAD_ROW(buf, rr)                                                     \
    {                                                                         \
        const float* xr_ = xb + (rr) * HW + pb + cq2 * HW2;                   \
        _Pragma("unroll") for (int ks_ = 0; ks_ < 8; ++ks_) {                 \
            const float* p_ = xr_ + ks_ * 8 * HW2;                            \
            buf[ks_][0] = __float_as_uint(p_[0]);                             \
            buf[ks_][1] = __float_as_uint(p_[8]);                             \
            buf[ks_][2] = __float_as_uint(p_[HW2]);                           \
            buf[ks_][3] = __float_as_uint(p_[HW2 + 8]);                       \
        }                                                                     \
    }

#define CVT_BUF(buf)                                                          \
    {                                                                         \
        _Pragma("unroll") for (int ks_ = 0; ks_ < 8; ++ks_)                   \
        _Pragma("unroll") for (int i_ = 0; i_ < 4; ++i_)                      \
            buf[ks_][i_] = f2tf(__uint_as_float(buf[ks_][i_]));               \
    }

#define EPILOGUE(A, o_)                                                       \
    {                                                                         \
        float* sb_ = s_epi[epar];                                             \
        epar ^= 1;                                                            \
        sb_[pb * 9 + cq2]           = A[0];                                   \
        sb_[pb * 9 + cq2 + 1]       = A[1];                                   \
        sb_[(pb + 8) * 9 + cq2]     = A[2];                                   \
        sb_[(pb + 8) * 9 + cq2 + 1] = A[3];                                   \
        __syncthreads();                                                      \
        if (tid < HW) {                                                       \
            float s_ = bv;                                                    \
            _Pragma("unroll") for (int dw_ = 0; dw_ < 7; ++dw_) {             \
                const int p_ = tid + dw_ - 3;                                 \
                if ((unsigned)p_ < (unsigned)HW) s_ += sb_[p_ * 9 + dw_];     \
            }                                                                 \
            outb[(o_) * HW + tid] = s_;                                       \
        }                                                                     \
    }

#define BODY(cur, nxt)                                                        \
    {                                                                         \
        if (r < rhi) LOAD_ROW(nxt, r + 1);                                    \
        CVT_BUF(cur);                                                         \
        _Pragma("unroll") for (int j_ = 0; j_ < 7; ++j_) {                    \
            const int o_ = r - 3 + j_;                                        \
            if (o_ >= ostart && o_ < oend) {                                  \
                const int dh_ = 6 - j_;                                       \
                _Pragma("unroll") for (int ks_ = 0; ks_ < 8; ++ks_) {         \
                    const unsigned long long bb_ = s_bw[dh_][ks_][lane];      \
                    mma8(acc[j_], cur[ks_],                                   \
                         (uint32_t)bb_, (uint32_t)(bb_ >> 32));               \
                }                                                             \
            }                                                                 \
        }                                                                     \
        if (r - 3 >= ostart) EPILOGUE(acc[0], r - 3);                         \
        _Pragma("unroll") for (int j_ = 0; j_ < 6; ++j_)                      \
        _Pragma("unroll") for (int k_ = 0; k_ < 4; ++k_)                      \
            acc[j_][k_] = acc[j_ + 1][k_];                                    \
        _Pragma("unroll") for (int k_ = 0; k_ < 4; ++k_)                      \
            acc[6][k_] = 0.f;                                                 \
    }

    LOAD_ROW(ab0, rlo);
    int r = rlo;
    while (true) {
        BODY(ab0, ab1);
        ++r;
        if (r > rhi) break;
        BODY(ab1, ab0);
        ++r;
        if (r > rhi) break;
    }

    // tail: after final shift, acc[j] holds o = rhi - 2 + j
#pragma unroll
    for (int jj = 0; jj < 6; ++jj) {
        const int o = rhi - 2 + jj;
        if (o >= ostart && o < oend) EPILOGUE(acc[jj], o);
    }
}

extern "C" void kernel_launch(void* const* d_in, const int* in_sizes, int n_in,
                              void* d_out, int out_size) {
    const float* x    = (const float*)d_in[0];   // (64, 64, 128, 128)
    const float* w    = (const float*)d_in[1];   // (64, 7, 7)
    const float* bias = (const float*)d_in[2];   // (1,)
    float* out = (float*)d_out;                  // (64, 128, 128)

    dim3 grid(HW / BAND, 64);                    // 4 x 64 = 256 CTAs
    conv7x7_mma256<<<grid, NT>>>(x, w, bias, out);
}

// round 10
// speedup vs baseline: 1.0947x; 1.0947x over previous
#include <cuda_runtime.h>
#include <cstdint>

// 7x7 single-out-channel conv via mma.sync tf32 implicit GEMM.
// Round 10: split K (channels) across warp pairs so B fragments live in
// registers permanently (no per-row LDS stream). 512 threads = 8 m-tiles x
// 2 ks-quads; partial D merged in the smem shift-sum epilogue.
// CTA = 32 output rows of one image; grid (4, 64).

#define HW 128
#define HW2 (HW * HW)
#define C_DIM 64
#define BAND 32
#define NT 512

static __device__ __forceinline__ uint32_t f2tf(float v) {
    uint32_t r;
    asm("cvt.rna.tf32.f32 %0, %1;" : "=r"(r) : "f"(v));
    return r;
}

static __device__ __forceinline__ void mma8(float (&d)[4], const uint32_t (&a)[4],
                                            uint32_t b0, uint32_t b1) {
    asm("mma.sync.aligned.m16n8k8.row.col.f32.tf32.tf32.f32 "
        "{%0,%1,%2,%3}, {%4,%5,%6,%7}, {%8,%9}, {%0,%1,%2,%3};"
        : "+f"(d[0]), "+f"(d[1]), "+f"(d[2]), "+f"(d[3])
        : "r"(a[0]), "r"(a[1]), "r"(a[2]), "r"(a[3]), "r"(b0), "r"(b1));
}

__global__ void __launch_bounds__(NT, 1)
conv7x7_mma512(const float* __restrict__ x, const float* __restrict__ w,
               const float* __restrict__ bias, float* __restrict__ out)
{
    // partial D: [buffer][kp][pixel][dw(pitch 9)]
    __shared__ float s_part[2][2][HW][9];

    const int tid  = threadIdx.x;
    const int wid  = tid >> 5;
    const int lane = tid & 31;
    const int g    = lane >> 2;       // pixel-within-tile row / n-index
    const int q    = lane & 3;        // k-quad
    const int t    = wid & 7;         // m-tile (16 pixels)
    const int kp   = wid >> 3;        // ks-quad group: channels kp*32..kp*32+31
    const int pb   = t * 16 + g;      // this thread's pixel rows: pb, pb+8

    const int b      = blockIdx.y;
    const int ostart = blockIdx.x * BAND;
    const int oend   = ostart + BAND;
    const int rlo    = (ostart - 3 < 0) ? 0 : ostart - 3;
    const int rhi    = (oend + 2 > HW - 1) ? HW - 1 : oend + 2;

    // ---- B fragments resident in registers: k-index q <-> channel c0+2q,
    //      k-index q+4 <-> channel c0+2q+1 (same perm as A loads); n = g = dw ----
    uint32_t bw[7][4][2];
#pragma unroll
    for (int dh = 0; dh < 7; ++dh)
#pragma unroll
        for (int i = 0; i < 4; ++i) {
            const int c = (kp * 4 + i) * 8 + 2 * q;
            bw[dh][i][0] = (g < 7) ? f2tf(w[c * 49 + dh * 7 + g]) : 0u;
            bw[dh][i][1] = (g < 7) ? f2tf(w[(c + 1) * 49 + dh * 7 + g]) : 0u;
        }

    const float* xw = x + (size_t)b * C_DIM * HW2
                        + (size_t)(kp * 32 + 2 * q) * HW2 + pb;
    float* outb = out + (size_t)b * HW2;
    const float bv = bias[0];

    float acc[7][4];
#pragma unroll
    for (int j = 0; j < 7; ++j)
#pragma unroll
        for (int k2 = 0; k2 < 4; ++k2) acc[j][k2] = 0.f;

    uint32_t av[4][4];
#pragma unroll
    for (int i = 0; i < 4; ++i) {
        const float* p = xw + i * 8 * HW2 + rlo * HW;
        av[i][0] = __float_as_uint(p[0]);
        av[i][1] = __float_as_uint(p[8]);
        av[i][2] = __float_as_uint(p[HW2]);
        av[i][3] = __float_as_uint(p[HW2 + 8]);
    }

    int epar = 0;

#define EPI(A, o_)                                                            \
    {                                                                         \
        s_part[epar][kp][pb][2 * q]         = A[0];                           \
        s_part[epar][kp][pb][2 * q + 1]     = A[1];                           \
        s_part[epar][kp][pb + 8][2 * q]     = A[2];                           \
        s_part[epar][kp][pb + 8][2 * q + 1] = A[3];                           \
        __syncthreads();                                                      \
        if (tid < HW) {                                                       \
            float s_ = bv;                                                    \
            _Pragma("unroll") for (int dw_ = 0; dw_ < 7; ++dw_) {             \
                const int p_ = tid + dw_ - 3;                                 \
                if ((unsigned)p_ < (unsigned)HW)                              \
                    s_ += s_part[epar][0][p_][dw_] + s_part[epar][1][p_][dw_];\
            }                                                                 \
            outb[(o_) * HW + tid] = s_;                                       \
        }                                                                     \
        epar ^= 1;                                                            \
    }

    for (int r = rlo; r <= rhi; ++r) {
#pragma unroll
        for (int i = 0; i < 4; ++i) {
            uint32_t tmp[4];
#pragma unroll
            for (int k2 = 0; k2 < 4; ++k2)
                tmp[k2] = f2tf(__uint_as_float(av[i][k2]));
            // reload same regs for next row (consumed into tmp already)
            if (r < rhi) {
                const float* p = xw + i * 8 * HW2 + (r + 1) * HW;
                av[i][0] = __float_as_uint(p[0]);
                av[i][1] = __float_as_uint(p[8]);
                av[i][2] = __float_as_uint(p[HW2]);
                av[i][3] = __float_as_uint(p[HW2 + 8]);
            }
#pragma unroll
            for (int j = 0; j < 7; ++j) {
                const int o = r - 3 + j;
                if (o >= ostart && o < oend)
                    mma8(acc[j], tmp, bw[6 - j][i][0], bw[6 - j][i][1]);
            }
        }

        if (r - 3 >= ostart) EPI(acc[0], r - 3);

#pragma unroll
        for (int j = 0; j < 6; ++j)
#pragma unroll
            for (int k2 = 0; k2 < 4; ++k2) acc[j][k2] = acc[j + 1][k2];
#pragma unroll
        for (int k2 = 0; k2 < 4; ++k2) acc[6][k2] = 0.f;
    }

    // tail: after final shift, acc[jj] holds o = rhi - 2 + jj
#pragma unroll
    for (int jj = 0; jj < 6; ++jj) {
        const int o = rhi - 2 + jj;
        if (o >= ostart && o < oend) EPI(acc[jj], o);
    }
#undef EPI
}

extern "C" void kernel_launch(void* const* d_in, const int* in_sizes, int n_in,
                              void* d_out, int out_size) {
    const float* x    = (const float*)d_in[0];   // (64, 64, 128, 128)
    const float* w    = (const float*)d_in[1];   // (64, 7, 7)
    const float* bias = (const float*)d_in[2];   // (1,)
    float* out = (float*)d_out;                  // (64, 128, 128)

    dim3 grid(HW / BAND, 64);                    // 4 x 64 = 256 CTAs
    conv7x7_mma512<<<grid, NT>>>(x, w, bias, out);
}

// round 11
// speedup vs baseline: 1.2196x; 1.1141x over previous
#include <cuda_runtime.h>
#include <cstdint>

// 7x7 single-out-channel conv via mma.sync tf32 implicit GEMM.
// Round 11: BAND=64 (single wave, 128 CTAs), 7-phase unrolled row loop with
// rotated accumulator indices (no ring shift), incremental row pointers.
// 512 threads = 8 m-tiles x 2 k-halves; B fragments register-resident.

#define HW 128
#define HW2 (HW * HW)
#define C_DIM 64
#define BAND 64
#define NT 512

static __device__ __forceinline__ uint32_t f2tf(float v) {
    uint32_t r;
    asm("cvt.rna.tf32.f32 %0, %1;" : "=r"(r) : "f"(v));
    return r;
}

static __device__ __forceinline__ void mma8(float (&d)[4], const uint32_t (&a)[4],
                                            uint32_t b0, uint32_t b1) {
    asm("mma.sync.aligned.m16n8k8.row.col.f32.tf32.tf32.f32 "
        "{%0,%1,%2,%3}, {%4,%5,%6,%7}, {%8,%9}, {%0,%1,%2,%3};"
        : "+f"(d[0]), "+f"(d[1]), "+f"(d[2]), "+f"(d[3])
        : "r"(a[0]), "r"(a[1]), "r"(a[2]), "r"(a[3]), "r"(b0), "r"(b1));
}

__global__ void __launch_bounds__(NT, 1)
conv7x7_mma64(const float* __restrict__ x, const float* __restrict__ w,
              const float* __restrict__ bias, float* __restrict__ out)
{
    // partial D: [buffer][kp][pixel][dw(pitch 9)]
    __shared__ float s_part[2][2][HW][9];

    const int tid  = threadIdx.x;
    const int wid  = tid >> 5;
    const int lane = tid & 31;
    const int g    = lane >> 2;       // pixel-within-tile row / n-index
    const int q    = lane & 3;        // k-quad
    const int t    = wid & 7;         // m-tile (16 pixels)
    const int kp   = wid >> 3;        // channel half: kp*32 .. kp*32+31
    const int pb   = t * 16 + g;      // thread's pixel rows: pb, pb+8

    const int b      = blockIdx.y;
    const int ostart = blockIdx.x * BAND;
    const int oend   = ostart + BAND;
    const int rlo    = (ostart - 3 < 0) ? 0 : ostart - 3;
    const int rhi    = (oend + 2 > HW - 1) ? HW - 1 : oend + 2;

    // ---- B fragments resident in registers ----
    uint32_t bw[7][4][2];
#pragma unroll
    for (int dh = 0; dh < 7; ++dh)
#pragma unroll
        for (int i = 0; i < 4; ++i) {
            const int c = (kp * 4 + i) * 8 + 2 * q;
            bw[dh][i][0] = (g < 7) ? f2tf(w[c * 49 + dh * 7 + g]) : 0u;
            bw[dh][i][1] = (g < 7) ? f2tf(w[(c + 1) * 49 + dh * 7 + g]) : 0u;
        }

    const float* xw = x + (size_t)b * C_DIM * HW2
                        + (size_t)(kp * 32 + 2 * q) * HW2 + pb;
    float* outb = out + (size_t)b * HW2;
    const float bv = bias[0];

    float acc[7][4];
#pragma unroll
    for (int j = 0; j < 7; ++j)
#pragma unroll
        for (int k2 = 0; k2 < 4; ++k2) acc[j][k2] = 0.f;

    // incremental row pointers, one per 8-channel k-step block
    const float* pA[4];
    uint32_t av[4][4];
#pragma unroll
    for (int i = 0; i < 4; ++i) {
        pA[i] = xw + i * 8 * HW2 + rlo * HW;
        av[i][0] = __float_as_uint(pA[i][0]);
        av[i][1] = __float_as_uint(pA[i][8]);
        av[i][2] = __float_as_uint(pA[i][HW2]);
        av[i][3] = __float_as_uint(pA[i][HW2 + 8]);
        pA[i] += HW;      // now points at row rlo+1
    }

    int epar = 0;
    int r = rlo;

#define PHASE(P)                                                              \
    {                                                                         \
        if (r <= rhi) {                                                       \
            _Pragma("unroll") for (int i_ = 0; i_ < 4; ++i_) {                \
                uint32_t tmp_[4];                                             \
                _Pragma("unroll") for (int k_ = 0; k_ < 4; ++k_)              \
                    tmp_[k_] = f2tf(__uint_as_float(av[i_][k_]));             \
                if (r < rhi) {                                                \
                    av[i_][0] = __float_as_uint(pA[i_][0]);                   \
                    av[i_][1] = __float_as_uint(pA[i_][8]);                   \
                    av[i_][2] = __float_as_uint(pA[i_][HW2]);                 \
                    av[i_][3] = __float_as_uint(pA[i_][HW2 + 8]);             \
                    pA[i_] += HW;                                             \
                }                                                             \
                _Pragma("unroll") for (int j_ = 0; j_ < 7; ++j_) {            \
                    const int o_ = r - 3 + j_;                                \
                    if (o_ >= ostart && o_ < oend)                            \
                        mma8(acc[(P + j_) % 7], tmp_,                         \
                             bw[6 - j_][i_][0], bw[6 - j_][i_][1]);           \
                }                                                             \
            }                                                                 \
        }                                                                     \
        const int o0_ = r - 3;                                                \
        if (o0_ >= ostart && o0_ < oend) {                                    \
            float (&A_)[4] = acc[(P) % 7];                                    \
            s_part[epar][kp][pb][2 * q]         = A_[0];                      \
            s_part[epar][kp][pb][2 * q + 1]     = A_[1];                      \
            s_part[epar][kp][pb + 8][2 * q]     = A_[2];                      \
            s_part[epar][kp][pb + 8][2 * q + 1] = A_[3];                      \
            __syncthreads();                                                  \
            if (tid < HW) {                                                   \
                float s_ = bv;                                                \
                _Pragma("unroll") for (int dw_ = 0; dw_ < 7; ++dw_) {         \
                    const int p_ = tid + dw_ - 3;                             \
                    if ((unsigned)p_ < (unsigned)HW)                          \
                        s_ += s_part[epar][0][p_][dw_]                        \
                            + s_part[epar][1][p_][dw_];                       \
                }                                                             \
                outb[o0_ * HW + tid] = s_;                                    \
            }                                                                 \
            _Pragma("unroll") for (int k_ = 0; k_ < 4; ++k_)                  \
                A_[k_] = 0.f;                                                 \
            epar ^= 1;                                                        \
        }                                                                     \
        ++r;                                                                  \
    }

    // 70 iterations = 10 x 7 phases covers both bands:
    //   top band:    r = 0..69   (rows 0..66 live, o 0..63 emitted in-loop)
    //   bottom band: r = 61..130 (rows 61..127 live, o 64..127 incl. tail)
#pragma unroll 1
    for (int ot = 0; ot < 10; ++ot) {
        PHASE(0) PHASE(1) PHASE(2) PHASE(3) PHASE(4) PHASE(5) PHASE(6)
    }
#undef PHASE
}

extern "C" void kernel_launch(void* const* d_in, const int* in_sizes, int n_in,
                              void* d_out, int out_size) {
    const float* x    = (const float*)d_in[0];   // (64, 64, 128, 128)
    const float* w    = (const float*)d_in[1];   // (64, 7, 7)
    const float* bias = (const float*)d_in[2];   // (1,)
    float* out = (float*)d_out;                  // (64, 128, 128)

    dim3 grid(HW / BAND, 64);                    // 2 x 64 = 128 CTAs, one wave
    conv7x7_mma64<<<grid, NT>>>(x, w, bias, out);
}